// round 5
// baseline (speedup 1.0000x reference)
#include <cuda_runtime.h>
#include <math.h>

#define B_     8
#define N_     4096
#define ALPHA  1.05f
#define JC     8               // j-dimension split factor
#define JCHUNK (N_ / JC)       // 512 candidates per block
#define PAIRS  (JCHUNK / 2)    // 256 candidate pairs
#define QPT    2               // queries per thread

// Scratch (no device allocations allowed)
// Transposed partial layout: g_part[((b*JC + jc)*6 + slot) * N_ + i]
__device__ float g_part[B_ * JC * 6 * N_];
__device__ float g_value[B_ * N_];

// ---- f32x2 helpers ---------------------------------------------------------
__device__ __forceinline__ double pk2d(float lo, float hi) {
    double d;
    asm("mov.b64 %0, {%1, %2};" : "=d"(d) : "f"(lo), "f"(hi));
    return d;
}
__device__ __forceinline__ void upk2(unsigned long long v, float& lo, float& hi) {
    asm("mov.b64 {%0, %1}, %2;" : "=f"(lo), "=f"(hi) : "l"(v));
}
__device__ __forceinline__ unsigned long long fma2(unsigned long long a,
                                                   unsigned long long b,
                                                   unsigned long long c) {
    unsigned long long d;
    asm("fma.rn.f32x2 %0, %1, %2, %3;" : "=l"(d) : "l"(a), "l"(b), "l"(c));
    return d;
}

// Sorted ascending top-6 insert; caller guarantees d < b5.
__device__ __forceinline__ void ins6(float d, float& b0, float& b1, float& b2,
                                     float& b3, float& b4, float& b5)
{
    b5 = d;
    float t;
    t = fminf(b4, b5); b5 = fmaxf(b4, b5); b4 = t;
    t = fminf(b3, b4); b4 = fmaxf(b3, b4); b3 = t;
    t = fminf(b2, b3); b3 = fmaxf(b2, b3); b2 = t;
    t = fminf(b1, b2); b2 = fmaxf(b1, b2); b1 = t;
    t = fminf(b0, b1); b1 = fmaxf(b0, b1); b0 = t;
}

// ---------------------------------------------------------------------------
// Kernel 1: partial kNN in reduced space r = ||pj||^2 - 2 pi.pj.
// Pre-packed pairwise candidates in smem; each thread carries TWO query
// points, so one candidate load feeds 4 (i,j) pairs with two independent
// FFMA2 dependency chains.
// ---------------------------------------------------------------------------
__global__ __launch_bounds__(128) void knn_part_kernel(const float* __restrict__ pc)
{
    __shared__ double2 sA[PAIRS];   // ((x0,x1), (y0,y1))  4 KB
    __shared__ double2 sB[PAIRS];   // ((z0,z1), (w0,w1))  4 KB, w = |p|^2

    const int b  = blockIdx.z;
    const int jc = blockIdx.y;
    const float* __restrict__ p  = pc + (size_t)b * N_ * 3;
    const float* __restrict__ pj = p + (size_t)jc * JCHUNK * 3;

    for (int j = threadIdx.x; j < PAIRS; j += 128) {
        float x0 = __ldg(pj + 6 * j + 0), y0 = __ldg(pj + 6 * j + 1), z0 = __ldg(pj + 6 * j + 2);
        float x1 = __ldg(pj + 6 * j + 3), y1 = __ldg(pj + 6 * j + 4), z1 = __ldg(pj + 6 * j + 5);
        float w0 = fmaf(x0, x0, fmaf(y0, y0, z0 * z0));
        float w1 = fmaf(x1, x1, fmaf(y1, y1, z1 * z1));
        sA[j] = make_double2(pk2d(x0, x1), pk2d(y0, y1));
        sB[j] = make_double2(pk2d(z0, z1), pk2d(w0, w1));
    }
    __syncthreads();

    // Two query points per thread, strided by 128 for coalesced stores.
    const int i0 = blockIdx.x * (128 * QPT) + threadIdx.x;
    const int i1 = i0 + 128;

    const float x0q = __ldg(p + 3 * i0), y0q = __ldg(p + 3 * i0 + 1), z0q = __ldg(p + 3 * i0 + 2);
    const float x1q = __ldg(p + 3 * i1), y1q = __ldg(p + 3 * i1 + 1), z1q = __ldg(p + 3 * i1 + 2);

    const unsigned long long nx0 = __double_as_longlong(pk2d(-2.f * x0q, -2.f * x0q));
    const unsigned long long ny0 = __double_as_longlong(pk2d(-2.f * y0q, -2.f * y0q));
    const unsigned long long nz0 = __double_as_longlong(pk2d(-2.f * z0q, -2.f * z0q));
    const unsigned long long nx1 = __double_as_longlong(pk2d(-2.f * x1q, -2.f * x1q));
    const unsigned long long ny1 = __double_as_longlong(pk2d(-2.f * y1q, -2.f * y1q));
    const unsigned long long nz1 = __double_as_longlong(pk2d(-2.f * z1q, -2.f * z1q));

    const float INF = __int_as_float(0x7f800000);
    float a0 = INF, a1 = INF, a2 = INF, a3 = INF, a4 = INF, a5 = INF;   // query 0
    float c0 = INF, c1 = INF, c2 = INF, c3 = INF, c4 = INF, c5 = INF;   // query 1

#pragma unroll 8
    for (int j = 0; j < PAIRS; ++j) {
        double2 a = sA[j];
        double2 c = sB[j];
        const unsigned long long ax = __double_as_longlong(a.x);
        const unsigned long long ay = __double_as_longlong(a.y);
        const unsigned long long cz = __double_as_longlong(c.x);
        const unsigned long long cw = __double_as_longlong(c.y);

        unsigned long long d0 = fma2(nx0, ax, fma2(ny0, ay, fma2(nz0, cz, cw)));
        unsigned long long d1 = fma2(nx1, ax, fma2(ny1, ay, fma2(nz1, cz, cw)));

        float l0, h0, l1, h1;
        upk2(d0, l0, h0);
        upk2(d1, l1, h1);

        if (fminf(l0, h0) < a5) {
            if (l0 < a5) ins6(l0, a0, a1, a2, a3, a4, a5);
            if (h0 < a5) ins6(h0, a0, a1, a2, a3, a4, a5);
        }
        if (fminf(l1, h1) < c5) {
            if (l1 < c5) ins6(l1, c0, c1, c2, c3, c4, c5);
            if (h1 < c5) ins6(h1, c0, c1, c2, c3, c4, c5);
        }
    }

    // Transposed, fully coalesced partial stores.
    float* __restrict__ o0 = g_part + ((size_t)(b * JC + jc) * 6) * N_ + i0;
    o0[0 * N_] = a0; o0[1 * N_] = a1; o0[2 * N_] = a2;
    o0[3 * N_] = a3; o0[4 * N_] = a4; o0[5 * N_] = a5;
    float* __restrict__ o1 = g_part + ((size_t)(b * JC + jc) * 6) * N_ + i1;
    o1[0 * N_] = c0; o1[1 * N_] = c1; o1[2 * N_] = c2;
    o1[3 * N_] = c3; o1[4 * N_] = c4; o1[5 * N_] = c5;
}

// ---------------------------------------------------------------------------
// Kernel 2: parallel merge — one thread per point. JC*6 coalesced loads,
// top-6 of them, drop smallest (self), add back ||p_i||^2.
// ---------------------------------------------------------------------------
__global__ __launch_bounds__(256) void merge_kernel(const float* __restrict__ pc)
{
    const int gid = blockIdx.x * 256 + threadIdx.x;   // b*N + i
    const int b   = gid >> 12;
    const int i   = gid & (N_ - 1);

    const float INF = __int_as_float(0x7f800000);
    float c0 = INF, c1 = INF, c2 = INF, c3 = INF, c4 = INF, c5 = INF;

#pragma unroll
    for (int t = 0; t < JC * 6; ++t) {
        float d = g_part[((size_t)(b * JC * 6 + t)) * N_ + i];
        if (d < c5) ins6(d, c0, c1, c2, c3, c4, c5);
    }
    const float* __restrict__ p = pc + (size_t)gid * 3;
    float x = __ldg(p), y = __ldg(p + 1), z = __ldg(p + 2);
    float xx = fmaf(x, x, fmaf(y, y, z * z));
    g_value[gid] = (c1 + c2 + c3 + c4 + c5) * 0.2f + xx;
}

// ---------------------------------------------------------------------------
// Kernel 3 (fused loss + final): single block, 1024 threads = 8 groups of
// 128 (one group per batch). Per-group mean/std(ddof=1) -> threshold ->
// masked mean * weight; thread 0 averages the 8 losses into out[0].
// ---------------------------------------------------------------------------
__global__ __launch_bounds__(1024) void loss_final_kernel(const float* __restrict__ weights,
                                                          float* __restrict__ out)
{
    const int tid = threadIdx.x;
    const int g   = tid >> 7;          // batch / group id, 0..7
    const int lt  = tid & 127;         // lane within group
    const int wid = tid >> 5;          // warp id, 0..31 (4 warps per group)
    const float* __restrict__ v = g_value + g * N_;

    __shared__ float sh_s[32];
    __shared__ float sh_s2[32];
    __shared__ float sh_m[32];
    __shared__ float sh_thr[8];
    __shared__ float sh_loss[8];

    // Pass 1: per-group sum / sumsq (32 elements per thread).
    float s = 0.f, s2 = 0.f;
    for (int t = lt; t < N_; t += 128) {
        float x = v[t];
        s  += x;
        s2 = fmaf(x, x, s2);
    }
#pragma unroll
    for (int o = 16; o > 0; o >>= 1) {
        s  += __shfl_down_sync(0xffffffffu, s,  o);
        s2 += __shfl_down_sync(0xffffffffu, s2, o);
    }
    if ((tid & 31) == 0) { sh_s[wid] = s; sh_s2[wid] = s2; }
    __syncthreads();

    if (tid < 32) {
        // lane l holds warp l's partials; warps 4g..4g+3 belong to group g.
        float ws  = sh_s[tid];
        float ws2 = sh_s2[tid];
        ws  += __shfl_xor_sync(0xffffffffu, ws,  1);
        ws  += __shfl_xor_sync(0xffffffffu, ws,  2);
        ws2 += __shfl_xor_sync(0xffffffffu, ws2, 1);
        ws2 += __shfl_xor_sync(0xffffffffu, ws2, 2);
        if ((tid & 3) == 0) {
            float mean = ws / (float)N_;
            float var  = (ws2 - ws * ws / (float)N_) / (float)(N_ - 1);
            var = fmaxf(var, 0.f);
            sh_thr[tid >> 2] = mean + ALPHA * sqrtf(var);
        }
    }
    __syncthreads();

    // Pass 2: masked sum (value > threshold).
    const float thr = sh_thr[g];
    float m = 0.f;
    for (int t = lt; t < N_; t += 128) {
        float x = v[t];
        if (x > thr) m += x;
    }
#pragma unroll
    for (int o = 16; o > 0; o >>= 1)
        m += __shfl_down_sync(0xffffffffu, m, o);
    if ((tid & 31) == 0) sh_m[wid] = m;
    __syncthreads();

    if (tid < 32) {
        float wm = sh_m[tid];
        wm += __shfl_xor_sync(0xffffffffu, wm, 1);
        wm += __shfl_xor_sync(0xffffffffu, wm, 2);
        if ((tid & 3) == 0)
            sh_loss[tid >> 2] = (wm / (float)N_) * __ldg(weights + (tid >> 2));
    }
    __syncthreads();

    if (tid == 0) {
        float t = 0.f;
#pragma unroll
        for (int b = 0; b < B_; ++b) t += sh_loss[b];
        out[0] = t / (float)B_;
    }
}

extern "C" void kernel_launch(void* const* d_in, const int* in_sizes, int n_in,
                              void* d_out, int out_size)
{
    const float* pc      = (const float*)d_in[0];  // [8, 4096, 3] f32
    const float* weights = (const float*)d_in[1];  // [8] f32
    float* out = (float*)d_out;

    dim3 grid1(N_ / (128 * QPT), JC, B_);   // 16 x 8 x 8 = 1024 blocks
    knn_part_kernel<<<grid1, 128>>>(pc);
    merge_kernel<<<B_ * N_ / 256, 256>>>(pc);
    loss_final_kernel<<<1, 1024>>>(weights, out);
}

// round 6
// speedup vs baseline: 1.1238x; 1.1238x over previous
#include <cuda_runtime.h>
#include <math.h>

#define B_     8
#define N_     4096
#define ALPHA  1.05f
#define JC     4               // j-dimension split factor
#define JCHUNK (N_ / JC)       // 1024 candidates per block
#define PAIRS  (JCHUNK / 2)    // 512 candidate pairs

// Scratch (no device allocations allowed)
// Transposed partial layout: g_part[((b*JC + jc)*6 + slot) * N_ + i]
__device__ float g_part[B_ * JC * 6 * N_];
__device__ float g_value[B_ * N_];

// ---- f32x2 helpers ---------------------------------------------------------
__device__ __forceinline__ double pk2d(float lo, float hi) {
    double d;
    asm("mov.b64 %0, {%1, %2};" : "=d"(d) : "f"(lo), "f"(hi));
    return d;
}
__device__ __forceinline__ void upk2(unsigned long long v, float& lo, float& hi) {
    asm("mov.b64 {%0, %1}, %2;" : "=f"(lo), "=f"(hi) : "l"(v));
}
__device__ __forceinline__ unsigned long long fma2(unsigned long long a,
                                                   unsigned long long b,
                                                   unsigned long long c) {
    unsigned long long d;
    asm("fma.rn.f32x2 %0, %1, %2, %3;" : "=l"(d) : "l"(a), "l"(b), "l"(c));
    return d;
}
#define D2L(x) __double_as_longlong(x)

// Sorted ascending top-6 insert; caller guarantees d < b5.
__device__ __forceinline__ void ins6(float d, float& b0, float& b1, float& b2,
                                     float& b3, float& b4, float& b5)
{
    b5 = d;
    float t;
    t = fminf(b4, b5); b5 = fmaxf(b4, b5); b4 = t;
    t = fminf(b3, b4); b4 = fmaxf(b3, b4); b3 = t;
    t = fminf(b2, b3); b3 = fmaxf(b2, b3); b2 = t;
    t = fminf(b1, b2); b2 = fmaxf(b1, b2); b1 = t;
    t = fminf(b0, b1); b1 = fmaxf(b0, b1); b0 = t;
}

// ---------------------------------------------------------------------------
// Kernel 1: partial kNN in reduced space r = ||pj||^2 - 2 pi.pj (per-i
// constant shift of true distance; top-6 ordering unchanged).
// Hot loop processes GROUPS of 8 candidates (4 pre-packed pairs): 12 FFMA2
// for the distances, a 7-op fmin tree, and ONE guard branch per group.
// Only triggered groups rescan their 8 saved values.
// ---------------------------------------------------------------------------
__global__ __launch_bounds__(128) void knn_part_kernel(const float* __restrict__ pc)
{
    __shared__ double2 sA[PAIRS];   // ((x0,x1), (y0,y1))  8 KB
    __shared__ double2 sB[PAIRS];   // ((z0,z1), (w0,w1))  8 KB, w = |p|^2

    const int b  = blockIdx.z;
    const int jc = blockIdx.y;
    const float* __restrict__ p  = pc + (size_t)b * N_ * 3;
    const float* __restrict__ pj = p + (size_t)jc * JCHUNK * 3;

    for (int j = threadIdx.x; j < PAIRS; j += 128) {
        float x0 = __ldg(pj + 6 * j + 0), y0 = __ldg(pj + 6 * j + 1), z0 = __ldg(pj + 6 * j + 2);
        float x1 = __ldg(pj + 6 * j + 3), y1 = __ldg(pj + 6 * j + 4), z1 = __ldg(pj + 6 * j + 5);
        float w0 = fmaf(x0, x0, fmaf(y0, y0, z0 * z0));
        float w1 = fmaf(x1, x1, fmaf(y1, y1, z1 * z1));
        sA[j] = make_double2(pk2d(x0, x1), pk2d(y0, y1));
        sB[j] = make_double2(pk2d(z0, z1), pk2d(w0, w1));
    }
    __syncthreads();

    const int i  = blockIdx.x * 128 + threadIdx.x;
    const float xi = __ldg(p + 3 * i);
    const float yi = __ldg(p + 3 * i + 1);
    const float zi = __ldg(p + 3 * i + 2);
    const unsigned long long nx = D2L(pk2d(-2.f * xi, -2.f * xi));
    const unsigned long long ny = D2L(pk2d(-2.f * yi, -2.f * yi));
    const unsigned long long nz = D2L(pk2d(-2.f * zi, -2.f * zi));

    const float INF = __int_as_float(0x7f800000);
    float b0 = INF, b1 = INF, b2 = INF, b3 = INF, b4 = INF, b5 = INF;

#pragma unroll 2
    for (int j = 0; j < PAIRS; j += 4) {
        double2 a0 = sA[j    ], c0v = sB[j    ];
        double2 a1 = sA[j + 1], c1v = sB[j + 1];
        double2 a2 = sA[j + 2], c2v = sB[j + 2];
        double2 a3 = sA[j + 3], c3v = sB[j + 3];

        unsigned long long d0 = fma2(nx, D2L(a0.x), fma2(ny, D2L(a0.y), fma2(nz, D2L(c0v.x), D2L(c0v.y))));
        unsigned long long d1 = fma2(nx, D2L(a1.x), fma2(ny, D2L(a1.y), fma2(nz, D2L(c1v.x), D2L(c1v.y))));
        unsigned long long d2 = fma2(nx, D2L(a2.x), fma2(ny, D2L(a2.y), fma2(nz, D2L(c2v.x), D2L(c2v.y))));
        unsigned long long d3 = fma2(nx, D2L(a3.x), fma2(ny, D2L(a3.y), fma2(nz, D2L(c3v.x), D2L(c3v.y))));

        float l0, h0, l1, h1, l2, h2, l3, h3;
        upk2(d0, l0, h0);
        upk2(d1, l1, h1);
        upk2(d2, l2, h2);
        upk2(d3, l3, h3);

        float m01 = fminf(fminf(l0, h0), fminf(l1, h1));
        float m23 = fminf(fminf(l2, h2), fminf(l3, h3));
        float gmin = fminf(m01, m23);

        if (gmin < b5) {                       // one guard per 8 candidates
            if (l0 < b5) ins6(l0, b0, b1, b2, b3, b4, b5);
            if (h0 < b5) ins6(h0, b0, b1, b2, b3, b4, b5);
            if (l1 < b5) ins6(l1, b0, b1, b2, b3, b4, b5);
            if (h1 < b5) ins6(h1, b0, b1, b2, b3, b4, b5);
            if (l2 < b5) ins6(l2, b0, b1, b2, b3, b4, b5);
            if (h2 < b5) ins6(h2, b0, b1, b2, b3, b4, b5);
            if (l3 < b5) ins6(l3, b0, b1, b2, b3, b4, b5);
            if (h3 < b5) ins6(h3, b0, b1, b2, b3, b4, b5);
        }
    }

    // Transposed, fully coalesced partial store.
    float* __restrict__ out = g_part + ((size_t)(b * JC + jc) * 6) * N_ + i;
    out[0 * N_] = b0; out[1 * N_] = b1; out[2 * N_] = b2;
    out[3 * N_] = b3; out[4 * N_] = b4; out[5 * N_] = b5;
}

// ---------------------------------------------------------------------------
// Kernel 2: parallel merge — one thread per point. JC*6 coalesced loads,
// top-6 of them, drop smallest (self), add back ||p_i||^2.
// ---------------------------------------------------------------------------
__global__ __launch_bounds__(256) void merge_kernel(const float* __restrict__ pc)
{
    const int gid = blockIdx.x * 256 + threadIdx.x;   // b*N + i
    const int b   = gid >> 12;
    const int i   = gid & (N_ - 1);

    const float INF = __int_as_float(0x7f800000);
    float c0 = INF, c1 = INF, c2 = INF, c3 = INF, c4 = INF, c5 = INF;

#pragma unroll
    for (int t = 0; t < JC * 6; ++t) {
        float d = g_part[((size_t)(b * JC * 6 + t)) * N_ + i];
        if (d < c5) ins6(d, c0, c1, c2, c3, c4, c5);
    }
    const float* __restrict__ p = pc + (size_t)gid * 3;
    float x = __ldg(p), y = __ldg(p + 1), z = __ldg(p + 2);
    float xx = fmaf(x, x, fmaf(y, y, z * z));
    g_value[gid] = (c1 + c2 + c3 + c4 + c5) * 0.2f + xx;
}

// ---------------------------------------------------------------------------
// Kernel 3 (fused loss + final): single block, 1024 threads = 8 groups of
// 128 (one group per batch). Per-group mean/std(ddof=1) -> threshold ->
// masked mean * weight; thread 0 averages the 8 losses into out[0].
// ---------------------------------------------------------------------------
__global__ __launch_bounds__(1024) void loss_final_kernel(const float* __restrict__ weights,
                                                          float* __restrict__ out)
{
    const int tid = threadIdx.x;
    const int g   = tid >> 7;          // batch / group id, 0..7
    const int lt  = tid & 127;         // lane within group
    const int wid = tid >> 5;          // warp id, 0..31 (4 warps per group)
    const float* __restrict__ v = g_value + g * N_;

    __shared__ float sh_s[32];
    __shared__ float sh_s2[32];
    __shared__ float sh_m[32];
    __shared__ float sh_thr[8];
    __shared__ float sh_loss[8];

    float s = 0.f, s2 = 0.f;
    for (int t = lt; t < N_; t += 128) {
        float x = v[t];
        s  += x;
        s2 = fmaf(x, x, s2);
    }
#pragma unroll
    for (int o = 16; o > 0; o >>= 1) {
        s  += __shfl_down_sync(0xffffffffu, s,  o);
        s2 += __shfl_down_sync(0xffffffffu, s2, o);
    }
    if ((tid & 31) == 0) { sh_s[wid] = s; sh_s2[wid] = s2; }
    __syncthreads();

    if (tid < 32) {
        float ws  = sh_s[tid];
        float ws2 = sh_s2[tid];
        ws  += __shfl_xor_sync(0xffffffffu, ws,  1);
        ws  += __shfl_xor_sync(0xffffffffu, ws,  2);
        ws2 += __shfl_xor_sync(0xffffffffu, ws2, 1);
        ws2 += __shfl_xor_sync(0xffffffffu, ws2, 2);
        if ((tid & 3) == 0) {
            float mean = ws / (float)N_;
            float var  = (ws2 - ws * ws / (float)N_) / (float)(N_ - 1);
            var = fmaxf(var, 0.f);
            sh_thr[tid >> 2] = mean + ALPHA * sqrtf(var);
        }
    }
    __syncthreads();

    const float thr = sh_thr[g];
    float m = 0.f;
    for (int t = lt; t < N_; t += 128) {
        float x = v[t];
        if (x > thr) m += x;
    }
#pragma unroll
    for (int o = 16; o > 0; o >>= 1)
        m += __shfl_down_sync(0xffffffffu, m, o);
    if ((tid & 31) == 0) sh_m[wid] = m;
    __syncthreads();

    if (tid < 32) {
        float wm = sh_m[tid];
        wm += __shfl_xor_sync(0xffffffffu, wm, 1);
        wm += __shfl_xor_sync(0xffffffffu, wm, 2);
        if ((tid & 3) == 0)
            sh_loss[tid >> 2] = (wm / (float)N_) * __ldg(weights + (tid >> 2));
    }
    __syncthreads();

    if (tid == 0) {
        float t = 0.f;
#pragma unroll
        for (int b = 0; b < B_; ++b) t += sh_loss[b];
        out[0] = t / (float)B_;
    }
}

extern "C" void kernel_launch(void* const* d_in, const int* in_sizes, int n_in,
                              void* d_out, int out_size)
{
    const float* pc      = (const float*)d_in[0];  // [8, 4096, 3] f32
    const float* weights = (const float*)d_in[1];  // [8] f32
    float* out = (float*)d_out;

    dim3 grid1(N_ / 128, JC, B_);          // 32 x 4 x 8 = 1024 blocks
    knn_part_kernel<<<grid1, 128>>>(pc);
    merge_kernel<<<B_ * N_ / 256, 256>>>(pc);
    loss_final_kernel<<<1, 1024>>>(weights, out);
}

// round 8
// speedup vs baseline: 1.2793x; 1.1384x over previous
#include <cuda_runtime.h>
#include <math.h>

#define B_     8
#define N_     4096
#define ALPHA  1.05f
#define JC     8               // j-dimension split factor
#define JCHUNK (N_ / JC)       // 512 candidates per chunk
#define PAIRS  (JCHUNK / 2)    // 256 pairs
#define SUBS   256             // subsample size per tau half
#define CAP    32              // stack capacity (pairs) per thread

typedef unsigned long long ull;

// Scratch (no device allocations allowed)
__device__ float g_tau[B_ * 2 * N_];
__device__ float g_part[B_ * JC * 6 * N_];   // [((b*JC+jc)*6+slot)*N_ + i]
__device__ float g_value[B_ * N_];

// ---- packed f32x2 helpers ----------------------------------------------
__device__ __forceinline__ ull pk(float lo, float hi) {
    ull r; asm("mov.b64 %0,{%1,%2};" : "=l"(r) : "f"(lo), "f"(hi)); return r;
}
__device__ __forceinline__ void unpk(ull v, float& lo, float& hi) {
    asm("mov.b64 {%0,%1},%2;" : "=f"(lo), "=f"(hi) : "l"(v));
}
__device__ __forceinline__ ull fma2(ull a, ull b, ull c) {
    ull d; asm("fma.rn.f32x2 %0,%1,%2,%3;" : "=l"(d) : "l"(a), "l"(b), "l"(c)); return d;
}

// Branchless sorted-ascending top-6 "insert": b5 = min(b5,d), bubble down.
// If d >= old b5 the list is unchanged; no guard, no branch. 11 fma-pipe ops.
__device__ __forceinline__ void ins6m(float d, float& b0, float& b1, float& b2,
                                      float& b3, float& b4, float& b5)
{
    b5 = fminf(b5, d);
    float t;
    t = fminf(b4, b5); b5 = fmaxf(b4, b5); b4 = t;
    t = fminf(b3, b4); b4 = fmaxf(b3, b4); b3 = t;
    t = fminf(b2, b3); b3 = fmaxf(b2, b3); b2 = t;
    t = fminf(b1, b2); b2 = fmaxf(b1, b2); b1 = t;
    t = fminf(b0, b1); b1 = fmaxf(b0, b1); b0 = t;
}

// ---------------------------------------------------------------------------
// Kernel A: per-point cutoff tau. Each thread scans a 256-point subsample
// (stride 16, offset 8*half) exactly in reduced space and writes its 6th
// smallest. tau_i = min over the two halves is an upper bound on the global
// 6th-smallest reduced distance for point i.
// ---------------------------------------------------------------------------
__global__ __launch_bounds__(128) void tau_kernel(const float* __restrict__ pc)
{
    __shared__ float4 sq[SUBS];   // (x, y, z, |p|^2)

    const int b = blockIdx.z;
    const int h = blockIdx.y;
    const float* __restrict__ p = pc + (size_t)b * N_ * 3;

    for (int k = threadIdx.x; k < SUBS; k += 128) {
        int j = 16 * k + 8 * h;
        float x = __ldg(p + 3 * j), y = __ldg(p + 3 * j + 1), z = __ldg(p + 3 * j + 2);
        float w = fmaf(x, x, fmaf(y, y, z * z));
        sq[k] = make_float4(x, y, z, w);
    }
    __syncthreads();

    const int i  = blockIdx.x * 128 + threadIdx.x;
    const float xi = __ldg(p + 3 * i);
    const float yi = __ldg(p + 3 * i + 1);
    const float zi = __ldg(p + 3 * i + 2);
    const float nx = -2.f * xi, ny = -2.f * yi, nz = -2.f * zi;

    const float INF = __int_as_float(0x7f800000);
    float b0 = INF, b1 = INF, b2 = INF, b3 = INF, b4 = INF, b5 = INF;

#pragma unroll 4
    for (int k = 0; k < SUBS; ++k) {
        float4 q = sq[k];
        float d = fmaf(nx, q.x, fmaf(ny, q.y, fmaf(nz, q.z, q.w)));
        ins6m(d, b0, b1, b2, b3, b4, b5);
    }
    g_tau[(b * 2 + h) * N_ + i] = b5;
}

// ---------------------------------------------------------------------------
// Kernel B: branch-free full scan. Per pair of candidates: 3 fma.f32x2 for
// the reduced distances, one fminf, and a predicated shared-memory push of
// the pair when min(lo,hi) <= tau. No selection state in the hot loop.
// Finish: exact branchless top-6 over the (few) pushed values.
// ---------------------------------------------------------------------------
__global__ __launch_bounds__(128) void knn_scan_kernel(const float* __restrict__ pc)
{
    __shared__ ulonglong2 sXY[PAIRS];      // (X=(x0,x1), Y=(y0,y1))  4 KB
    __shared__ ulonglong2 sZW[PAIRS];      // (Z=(z0,z1), W=(w0,w1))  4 KB
    __shared__ float2 stk[CAP * 128];      // 32 KB: entry e, thread t at [e*128+t]

    const int b  = blockIdx.z;
    const int jc = blockIdx.y;
    const float* __restrict__ p  = pc + (size_t)b * N_ * 3;
    const float* __restrict__ pj = p + (size_t)jc * JCHUNK * 3;

    for (int j = threadIdx.x; j < PAIRS; j += 128) {
        float x0 = __ldg(pj + 6 * j + 0), y0 = __ldg(pj + 6 * j + 1), z0 = __ldg(pj + 6 * j + 2);
        float x1 = __ldg(pj + 6 * j + 3), y1 = __ldg(pj + 6 * j + 4), z1 = __ldg(pj + 6 * j + 5);
        float w0 = fmaf(x0, x0, fmaf(y0, y0, z0 * z0));
        float w1 = fmaf(x1, x1, fmaf(y1, y1, z1 * z1));
        sXY[j] = make_ulonglong2(pk(x0, x1), pk(y0, y1));
        sZW[j] = make_ulonglong2(pk(z0, z1), pk(w0, w1));
    }
    __syncthreads();

    const int i  = blockIdx.x * 128 + threadIdx.x;
    const float xi = __ldg(p + 3 * i);
    const float yi = __ldg(p + 3 * i + 1);
    const float zi = __ldg(p + 3 * i + 2);
    const ull nx = pk(-2.f * xi, -2.f * xi);
    const ull ny = pk(-2.f * yi, -2.f * yi);
    const ull nz = pk(-2.f * zi, -2.f * zi);

    // Cutoff: min over the two subsample halves, bumped +1 ulp for safety
    // (arithmetic in both kernels is bit-identical, but be generous).
    float tau = fminf(g_tau[(b * 2 + 0) * N_ + i], g_tau[(b * 2 + 1) * N_ + i]);
    int tb = __float_as_int(tau);
    tb += (tb >= 0) ? 1 : -1;           // one ulp toward +inf
    tau = __int_as_float(tb);

    unsigned sbase = (unsigned)__cvta_generic_to_shared(stk);
    unsigned addr  = sbase + threadIdx.x * 8u;
    const unsigned tb0   = addr;
    const unsigned limit = addr + CAP * 1024u;

#pragma unroll 4
    for (int j = 0; j < PAIRS; ++j) {
        ulonglong2 xy = sXY[j];
        ulonglong2 zw = sZW[j];
        ull d2 = fma2(nx, xy.x, fma2(ny, xy.y, fma2(nz, zw.x, zw.y)));
        float lo, hi;
        unpk(d2, lo, hi);
        float pmin = fminf(lo, hi);
        // predicated push: if (pmin <= tau && addr < limit) { store pair; addr += 1024 }
        asm volatile(
            "{\n\t"
            ".reg .pred p;\n\t"
            "setp.le.f32 p, %1, %2;\n\t"
            "setp.lt.and.u32 p, %0, %3, p;\n\t"
            "@p st.shared.v2.f32 [%0], {%4, %5};\n\t"
            "@p add.u32 %0, %0, 1024;\n\t"
            "}"
            : "+r"(addr)
            : "f"(pmin), "f"(tau), "r"(limit), "f"(lo), "f"(hi)
            : "memory");
    }

    // Finish: exact branchless top-6 over pushed values.
    const int cnt = (int)((addr - tb0) >> 10);
    const float INF = __int_as_float(0x7f800000);
    float b0 = INF, b1 = INF, b2 = INF, b3 = INF, b4 = INF, b5 = INF;
    for (int e = 0; e < cnt; ++e) {
        float2 v = stk[e * 128 + threadIdx.x];
        ins6m(v.x, b0, b1, b2, b3, b4, b5);
        ins6m(v.y, b0, b1, b2, b3, b4, b5);
    }

    float* __restrict__ out = g_part + ((size_t)(b * JC + jc) * 6) * N_ + i;
    out[0 * N_] = b0; out[1 * N_] = b1; out[2 * N_] = b2;
    out[3 * N_] = b3; out[4 * N_] = b4; out[5 * N_] = b5;
}

// ---------------------------------------------------------------------------
// Kernel C: parallel merge — one thread per point. JC*6 coalesced loads,
// exact top-6, drop smallest (self), add back ||p_i||^2.
// ---------------------------------------------------------------------------
__global__ __launch_bounds__(256) void merge_kernel(const float* __restrict__ pc)
{
    const int gid = blockIdx.x * 256 + threadIdx.x;   // b*N + i
    const int b   = gid >> 12;
    const int i   = gid & (N_ - 1);

    const float INF = __int_as_float(0x7f800000);
    float c0 = INF, c1 = INF, c2 = INF, c3 = INF, c4 = INF, c5 = INF;

#pragma unroll
    for (int t = 0; t < JC * 6; ++t) {
        float d = g_part[((size_t)(b * JC * 6 + t)) * N_ + i];
        ins6m(d, c0, c1, c2, c3, c4, c5);
    }
    const float* __restrict__ p = pc + (size_t)gid * 3;
    float x = __ldg(p), y = __ldg(p + 1), z = __ldg(p + 2);
    float xx = fmaf(x, x, fmaf(y, y, z * z));
    g_value[gid] = (c1 + c2 + c3 + c4 + c5) * 0.2f + xx;
}

// ---------------------------------------------------------------------------
// Kernel D (fused loss + final): single block, 1024 threads = 8 groups of
// 128 (one per batch). Per-group mean/std(ddof=1) -> threshold -> masked
// mean * weight; thread 0 averages the 8 losses into out[0].
// ---------------------------------------------------------------------------
__global__ __launch_bounds__(1024) void loss_final_kernel(const float* __restrict__ weights,
                                                          float* __restrict__ out)
{
    const int tid = threadIdx.x;
    const int g   = tid >> 7;
    const int lt  = tid & 127;
    const int wid = tid >> 5;
    const float* __restrict__ v = g_value + g * N_;

    __shared__ float sh_s[32];
    __shared__ float sh_s2[32];
    __shared__ float sh_m[32];
    __shared__ float sh_thr[8];
    __shared__ float sh_loss[8];

    float s = 0.f, s2 = 0.f;
    for (int t = lt; t < N_; t += 128) {
        float x = v[t];
        s  += x;
        s2 = fmaf(x, x, s2);
    }
#pragma unroll
    for (int o = 16; o > 0; o >>= 1) {
        s  += __shfl_down_sync(0xffffffffu, s,  o);
        s2 += __shfl_down_sync(0xffffffffu, s2, o);
    }
    if ((tid & 31) == 0) { sh_s[wid] = s; sh_s2[wid] = s2; }
    __syncthreads();

    if (tid < 32) {
        float ws  = sh_s[tid];
        float ws2 = sh_s2[tid];
        ws  += __shfl_xor_sync(0xffffffffu, ws,  1);
        ws  += __shfl_xor_sync(0xffffffffu, ws,  2);
        ws2 += __shfl_xor_sync(0xffffffffu, ws2, 1);
        ws2 += __shfl_xor_sync(0xffffffffu, ws2, 2);
        if ((tid & 3) == 0) {
            float mean = ws / (float)N_;
            float var  = (ws2 - ws * ws / (float)N_) / (float)(N_ - 1);
            var = fmaxf(var, 0.f);
            sh_thr[tid >> 2] = mean + ALPHA * sqrtf(var);
        }
    }
    __syncthreads();

    const float thr = sh_thr[g];
    float m = 0.f;
    for (int t = lt; t < N_; t += 128) {
        float x = v[t];
        if (x > thr) m += x;
    }
#pragma unroll
    for (int o = 16; o > 0; o >>= 1)
        m += __shfl_down_sync(0xffffffffu, m, o);
    if ((tid & 31) == 0) sh_m[wid] = m;
    __syncthreads();

    if (tid < 32) {
        float wm = sh_m[tid];
        wm += __shfl_xor_sync(0xffffffffu, wm, 1);
        wm += __shfl_xor_sync(0xffffffffu, wm, 2);
        if ((tid & 3) == 0)
            sh_loss[tid >> 2] = (wm / (float)N_) * __ldg(weights + (tid >> 2));
    }
    __syncthreads();

    if (tid == 0) {
        float t = 0.f;
#pragma unroll
        for (int b = 0; b < B_; ++b) t += sh_loss[b];
        out[0] = t / (float)B_;
    }
}

extern "C" void kernel_launch(void* const* d_in, const int* in_sizes, int n_in,
                              void* d_out, int out_size)
{
    const float* pc      = (const float*)d_in[0];  // [8, 4096, 3] f32
    const float* weights = (const float*)d_in[1];  // [8] f32
    float* out = (float*)d_out;

    dim3 gridA(N_ / 128, 2, B_);           // 32 x 2 x 8 = 512 blocks
    tau_kernel<<<gridA, 128>>>(pc);
    dim3 gridB(N_ / 128, JC, B_);          // 32 x 8 x 8 = 2048 blocks
    knn_scan_kernel<<<gridB, 128>>>(pc);
    merge_kernel<<<B_ * N_ / 256, 256>>>(pc);
    loss_final_kernel<<<1, 1024>>>(weights, out);
}

// round 9
// speedup vs baseline: 1.3546x; 1.0589x over previous
#include <cuda_runtime.h>
#include <math.h>

#define B_     8
#define N_     4096
#define ALPHA  1.05f
#define JC     8               // j-dimension split factor
#define JCHUNK (N_ / JC)       // 512 candidates per chunk
#define PAIRS  (JCHUNK / 2)    // 256 pairs
#define SUBS   256             // tau subsample size
#define CAP    32              // stack capacity (pairs) per thread

typedef unsigned long long ull;

// Scratch (no device allocations allowed)
__device__ float g_tau[B_ * N_];
__device__ float g_part[B_ * JC * 6 * N_];   // [((b*JC+jc)*6+slot)*N_ + i]
__device__ float g_value[B_ * N_];

// ---- packed f32x2 helpers ----------------------------------------------
__device__ __forceinline__ ull pk(float lo, float hi) {
    ull r; asm("mov.b64 %0,{%1,%2};" : "=l"(r) : "f"(lo), "f"(hi)); return r;
}
__device__ __forceinline__ void unpk(ull v, float& lo, float& hi) {
    asm("mov.b64 {%0,%1},%2;" : "=f"(lo), "=f"(hi) : "l"(v));
}
__device__ __forceinline__ ull fma2(ull a, ull b, ull c) {
    ull d; asm("fma.rn.f32x2 %0,%1,%2,%3;" : "=l"(d) : "l"(a), "l"(b), "l"(c)); return d;
}

// Branchless sorted-ascending top-6 insert: b5 = min(b5,d), bubble down.
__device__ __forceinline__ void ins6m(float d, float& b0, float& b1, float& b2,
                                      float& b3, float& b4, float& b5)
{
    b5 = fminf(b5, d);
    float t;
    t = fminf(b4, b5); b5 = fmaxf(b4, b5); b4 = t;
    t = fminf(b3, b4); b4 = fmaxf(b3, b4); b3 = t;
    t = fminf(b2, b3); b3 = fmaxf(b2, b3); b2 = t;
    t = fminf(b1, b2); b2 = fmaxf(b1, b2); b1 = t;
    t = fminf(b0, b1); b1 = fmaxf(b0, b1); b0 = t;
}

// ---------------------------------------------------------------------------
// Kernel A: per-point cutoff tau = 6th smallest reduced distance over a
// 256-point subsample (stride 16). Upper bound on the global 6th smallest,
// computed with the same fma ordering as the scan kernel (bit-identical).
// ---------------------------------------------------------------------------
__global__ __launch_bounds__(128) void tau_kernel(const float* __restrict__ pc)
{
    __shared__ float4 sq[SUBS];   // (x, y, z, |p|^2)

    const int b = blockIdx.y;
    const float* __restrict__ p = pc + (size_t)b * N_ * 3;

    for (int k = threadIdx.x; k < SUBS; k += 128) {
        int j = 16 * k;
        float x = __ldg(p + 3 * j), y = __ldg(p + 3 * j + 1), z = __ldg(p + 3 * j + 2);
        float w = fmaf(x, x, fmaf(y, y, z * z));
        sq[k] = make_float4(x, y, z, w);
    }
    __syncthreads();

    const int i  = blockIdx.x * 128 + threadIdx.x;
    const float xi = __ldg(p + 3 * i);
    const float yi = __ldg(p + 3 * i + 1);
    const float zi = __ldg(p + 3 * i + 2);
    const float nx = -2.f * xi, ny = -2.f * yi, nz = -2.f * zi;

    const float INF = __int_as_float(0x7f800000);
    float b0 = INF, b1 = INF, b2 = INF, b3 = INF, b4 = INF, b5 = INF;

#pragma unroll 8
    for (int k = 0; k < SUBS; ++k) {
        float4 q = sq[k];
        float d = fmaf(nx, q.x, fmaf(ny, q.y, fmaf(nz, q.z, q.w)));
        ins6m(d, b0, b1, b2, b3, b4, b5);
    }
    g_tau[b * N_ + i] = b5;
}

// ---------------------------------------------------------------------------
// Kernel B: branch-free full scan. Per candidate pair: 3 fma.f32x2 for the
// reduced distances, one fminf, and a predicated shared push when
// min(lo,hi) <= tau. Exact branchless top-6 over pushed values at the end.
// ---------------------------------------------------------------------------
__global__ __launch_bounds__(128) void knn_scan_kernel(const float* __restrict__ pc)
{
    __shared__ ulonglong2 sXY[PAIRS];      // (X=(x0,x1), Y=(y0,y1))  4 KB
    __shared__ ulonglong2 sZW[PAIRS];      // (Z=(z0,z1), W=(w0,w1))  4 KB
    __shared__ float2 stk[CAP * 128];      // 32 KB push stacks

    const int b  = blockIdx.z;
    const int jc = blockIdx.y;
    const float* __restrict__ p  = pc + (size_t)b * N_ * 3;
    const float* __restrict__ pj = p + (size_t)jc * JCHUNK * 3;

    for (int j = threadIdx.x; j < PAIRS; j += 128) {
        float x0 = __ldg(pj + 6 * j + 0), y0 = __ldg(pj + 6 * j + 1), z0 = __ldg(pj + 6 * j + 2);
        float x1 = __ldg(pj + 6 * j + 3), y1 = __ldg(pj + 6 * j + 4), z1 = __ldg(pj + 6 * j + 5);
        float w0 = fmaf(x0, x0, fmaf(y0, y0, z0 * z0));
        float w1 = fmaf(x1, x1, fmaf(y1, y1, z1 * z1));
        sXY[j] = make_ulonglong2(pk(x0, x1), pk(y0, y1));
        sZW[j] = make_ulonglong2(pk(z0, z1), pk(w0, w1));
    }
    __syncthreads();

    const int i  = blockIdx.x * 128 + threadIdx.x;
    const float xi = __ldg(p + 3 * i);
    const float yi = __ldg(p + 3 * i + 1);
    const float zi = __ldg(p + 3 * i + 2);
    const ull nx = pk(-2.f * xi, -2.f * xi);
    const ull ny = pk(-2.f * yi, -2.f * yi);
    const ull nz = pk(-2.f * zi, -2.f * zi);

    // Cutoff (+1 ulp toward +inf for safety; arithmetic is bit-identical).
    float tau = g_tau[b * N_ + i];
    int tb = __float_as_int(tau);
    tb += (tb >= 0) ? 1 : -1;
    tau = __int_as_float(tb);

    unsigned sbase = (unsigned)__cvta_generic_to_shared(stk);
    unsigned addr  = sbase + threadIdx.x * 8u;
    const unsigned tb0   = addr;
    const unsigned limit = addr + CAP * 1024u;

#pragma unroll 8
    for (int j = 0; j < PAIRS; ++j) {
        ulonglong2 xy = sXY[j];
        ulonglong2 zw = sZW[j];
        ull d2 = fma2(nx, xy.x, fma2(ny, xy.y, fma2(nz, zw.x, zw.y)));
        float lo, hi;
        unpk(d2, lo, hi);
        float pmin = fminf(lo, hi);
        asm volatile(
            "{\n\t"
            ".reg .pred p;\n\t"
            "setp.le.f32 p, %1, %2;\n\t"
            "setp.lt.and.u32 p, %0, %3, p;\n\t"
            "@p st.shared.v2.f32 [%0], {%4, %5};\n\t"
            "@p add.u32 %0, %0, 1024;\n\t"
            "}"
            : "+r"(addr)
            : "f"(pmin), "f"(tau), "r"(limit), "f"(lo), "f"(hi)
            : "memory");
    }

    // Finish: exact branchless top-6 over pushed values.
    const int cnt = (int)((addr - tb0) >> 10);
    const float INF = __int_as_float(0x7f800000);
    float b0 = INF, b1 = INF, b2 = INF, b3 = INF, b4 = INF, b5 = INF;
    for (int e = 0; e < cnt; ++e) {
        float2 v = stk[e * 128 + threadIdx.x];
        ins6m(v.x, b0, b1, b2, b3, b4, b5);
        ins6m(v.y, b0, b1, b2, b3, b4, b5);
    }

    float* __restrict__ out = g_part + ((size_t)(b * JC + jc) * 6) * N_ + i;
    out[0 * N_] = b0; out[1 * N_] = b1; out[2 * N_] = b2;
    out[3 * N_] = b3; out[4 * N_] = b4; out[5 * N_] = b5;
}

// ---------------------------------------------------------------------------
// Kernel C: parallel merge — one thread per point. JC*6 coalesced loads,
// exact top-6, drop smallest (self), add back ||p_i||^2.
// ---------------------------------------------------------------------------
__global__ __launch_bounds__(256) void merge_kernel(const float* __restrict__ pc)
{
    const int gid = blockIdx.x * 256 + threadIdx.x;   // b*N + i
    const int b   = gid >> 12;
    const int i   = gid & (N_ - 1);

    const float INF = __int_as_float(0x7f800000);
    float c0 = INF, c1 = INF, c2 = INF, c3 = INF, c4 = INF, c5 = INF;

#pragma unroll
    for (int t = 0; t < JC * 6; ++t) {
        float d = g_part[((size_t)(b * JC * 6 + t)) * N_ + i];
        ins6m(d, c0, c1, c2, c3, c4, c5);
    }
    const float* __restrict__ p = pc + (size_t)gid * 3;
    float x = __ldg(p), y = __ldg(p + 1), z = __ldg(p + 2);
    float xx = fmaf(x, x, fmaf(y, y, z * z));
    g_value[gid] = (c1 + c2 + c3 + c4 + c5) * 0.2f + xx;
}

// ---------------------------------------------------------------------------
// Kernel D (fused loss + final): single block, 1024 threads = 8 groups of
// 128 (one per batch). Per-group mean/std(ddof=1) -> threshold -> masked
// mean * weight; thread 0 averages the 8 losses into out[0].
// ---------------------------------------------------------------------------
__global__ __launch_bounds__(1024) void loss_final_kernel(const float* __restrict__ weights,
                                                          float* __restrict__ out)
{
    const int tid = threadIdx.x;
    const int g   = tid >> 7;
    const int lt  = tid & 127;
    const int wid = tid >> 5;
    const float* __restrict__ v = g_value + g * N_;

    __shared__ float sh_s[32];
    __shared__ float sh_s2[32];
    __shared__ float sh_m[32];
    __shared__ float sh_thr[8];
    __shared__ float sh_loss[8];

    float s = 0.f, s2 = 0.f;
    for (int t = lt; t < N_; t += 128) {
        float x = v[t];
        s  += x;
        s2 = fmaf(x, x, s2);
    }
#pragma unroll
    for (int o = 16; o > 0; o >>= 1) {
        s  += __shfl_down_sync(0xffffffffu, s,  o);
        s2 += __shfl_down_sync(0xffffffffu, s2, o);
    }
    if ((tid & 31) == 0) { sh_s[wid] = s; sh_s2[wid] = s2; }
    __syncthreads();

    if (tid < 32) {
        float ws  = sh_s[tid];
        float ws2 = sh_s2[tid];
        ws  += __shfl_xor_sync(0xffffffffu, ws,  1);
        ws  += __shfl_xor_sync(0xffffffffu, ws,  2);
        ws2 += __shfl_xor_sync(0xffffffffu, ws2, 1);
        ws2 += __shfl_xor_sync(0xffffffffu, ws2, 2);
        if ((tid & 3) == 0) {
            float mean = ws / (float)N_;
            float var  = (ws2 - ws * ws / (float)N_) / (float)(N_ - 1);
            var = fmaxf(var, 0.f);
            sh_thr[tid >> 2] = mean + ALPHA * sqrtf(var);
        }
    }
    __syncthreads();

    const float thr = sh_thr[g];
    float m = 0.f;
    for (int t = lt; t < N_; t += 128) {
        float x = v[t];
        if (x > thr) m += x;
    }
#pragma unroll
    for (int o = 16; o > 0; o >>= 1)
        m += __shfl_down_sync(0xffffffffu, m, o);
    if ((tid & 31) == 0) sh_m[wid] = m;
    __syncthreads();

    if (tid < 32) {
        float wm = sh_m[tid];
        wm += __shfl_xor_sync(0xffffffffu, wm, 1);
        wm += __shfl_xor_sync(0xffffffffu, wm, 2);
        if ((tid & 3) == 0)
            sh_loss[tid >> 2] = (wm / (float)N_) * __ldg(weights + (tid >> 2));
    }
    __syncthreads();

    if (tid == 0) {
        float t = 0.f;
#pragma unroll
        for (int b = 0; b < B_; ++b) t += sh_loss[b];
        out[0] = t / (float)B_;
    }
}

extern "C" void kernel_launch(void* const* d_in, const int* in_sizes, int n_in,
                              void* d_out, int out_size)
{
    const float* pc      = (const float*)d_in[0];  // [8, 4096, 3] f32
    const float* weights = (const float*)d_in[1];  // [8] f32
    float* out = (float*)d_out;

    dim3 gridA(N_ / 128, B_);              // 32 x 8 = 256 blocks
    tau_kernel<<<gridA, 128>>>(pc);
    dim3 gridB(N_ / 128, JC, B_);          // 32 x 8 x 8 = 2048 blocks
    knn_scan_kernel<<<gridB, 128>>>(pc);
    merge_kernel<<<B_ * N_ / 256, 256>>>(pc);
    loss_final_kernel<<<1, 1024>>>(weights, out);
}